// round 2
// baseline (speedup 1.0000x reference)
#include <cuda_runtime.h>

// Problem constants
#define NN 64
#define CC 256
#define TT 64
#define VV 25
#define VP 28                  // padded V (float4/u64-friendly row stride: 112B)
#define NT (NN * TT)           // 4096 CTAs per block-kernel
#define ELEMS (NN * CC * TT * VV)

// Ping-pong scratch for the inter-block residual tensors (no cudaMalloc allowed)
__device__ float g_buf0[ELEMS];
__device__ float g_buf1[ELEMS];

// Packed fp32x2 FMA (sm_100+ only; ptxas never auto-fuses this — inline PTX required)
__device__ __forceinline__ unsigned long long ffma2(unsigned long long a,
                                                    unsigned long long b,
                                                    unsigned long long c) {
    unsigned long long d;
    asm("fma.rn.f32x2 %0, %1, %2, %3;" : "=l"(d) : "l"(a), "l"(b), "l"(c));
    return d;
}

__device__ __forceinline__ unsigned long long pack2(float x) {
    unsigned long long d;
    unsigned xu = __float_as_uint(x);
    asm("mov.b64 %0, {%1, %2};" : "=l"(d) : "r"(xu), "r"(xu));
    return d;
}

// Shared memory layout (floats):
//   sx:  CC*VP  (x slab, also the residual)
//   sy:  CC*VP  (y = x @ A^T, later reused as output staging)
//   sA:  640    (25x25 A matrix, padded)
//   wt:  32*257 (transposed W tile, 257-stride => conflict-free)
#define SX_OFF  0
#define SY_OFF  (CC * VP)
#define SA_OFF  (2 * CC * VP)
#define WT_OFF  (2 * CC * VP + 640)
#define SMEM_FLOATS (2 * CC * VP + 640 + 32 * 257)
#define SMEM_BYTES  (SMEM_FLOATS * 4)

__global__ void __launch_bounds__(256, 2)
ode_block_kernel(const float* __restrict__ in,   // residual input [N,C,T,V]
                 const float* __restrict__ Amat, // [V,V]
                 const float* __restrict__ w,    // [C,C] (row o, col c)
                 const float* __restrict__ b,    // [C]
                 float* __restrict__ out)        // [N,C,T,V]
{
    extern __shared__ float smem[];
    float* sx = smem + SX_OFF;
    float* sy = smem + SY_OFF;
    float* sA = smem + SA_OFF;
    float* wt = smem + WT_OFF;

    const int tid = threadIdx.x;
    const int nt  = blockIdx.x;
    const int n   = nt / TT;
    const int t   = nt - n * TT;
    // index(n,c,t,v) = ((n*C + c)*T + t)*V + v
    const long base = (long)n * (CC * TT * VV) + (long)t * VV;

    // ---- Load A (25x25) and the x slab [C][V] ----
    for (int i = tid; i < VV * VV; i += 256) sA[i] = Amat[i];
    for (int i = tid; i < CC * VV; i += 256) {
        int c = i / VV;
        int v = i - c * VV;
        sx[c * VP + v] = in[base + (long)c * (TT * VV) + v];
    }
    __syncthreads();

    // ---- Phase 1: y[c][v] = sum_u A[v][u] * x[c][u]  (thread c = tid) ----
    {
        float xr[VV];
#pragma unroll
        for (int u = 0; u < VV; u++) xr[u] = sx[tid * VP + u];
#pragma unroll
        for (int v = 0; v < VV; v++) {
            float s = 0.f;
#pragma unroll
            for (int u = 0; u < VV; u++) s = fmaf(sA[v * VV + u], xr[u], s);
            sy[tid * VP + v] = s;
        }
        // zero the padding lanes so packed-f32x2 reads are well-defined
        sy[tid * VP + 25] = 0.f;
        sy[tid * VP + 26] = 0.f;
        sy[tid * VP + 27] = 0.f;
    }
    __syncthreads();

    // ---- Phase 2: out[o][v] = sum_c w[o][c] * y[c][v], thread owns o = tid ----
    unsigned long long acc[13];
#pragma unroll
    for (int j = 0; j < 13; j++) acc[j] = 0ULL;

    for (int cc = 0; cc < CC; cc += 32) {
        // Stage transposed W tile: wt[cl][o] = w[o][cc+cl]
        // global read coalesced (consecutive cl), smem write conflict-free (stride 257)
        for (int i = tid; i < 32 * CC; i += 256) {
            int o  = i >> 5;
            int cl = i & 31;
            wt[cl * 257 + o] = w[o * CC + cc + cl];
        }
        __syncthreads();

#pragma unroll 4
        for (int cl = 0; cl < 32; cl++) {
            unsigned long long wv2 = pack2(wt[cl * 257 + tid]);   // conflict-free LDS
            const unsigned long long* yrow =
                reinterpret_cast<const unsigned long long*>(sy + (cc + cl) * VP); // broadcast
#pragma unroll
            for (int j = 0; j < 13; j++) acc[j] = ffma2(yrow[j], wv2, acc[j]);
        }
        __syncthreads();
    }

    // ---- Phase 3: epilogue relu(acc + b[o] + x[o][v]) ----
    float bias = b[tid];
    float rr[VV + 1];
#pragma unroll
    for (int j = 0; j < 13; j++) {
        unsigned long long a = acc[j];
        rr[2 * j]     = __uint_as_float((unsigned)(a & 0xffffffffULL));
        rr[2 * j + 1] = __uint_as_float((unsigned)(a >> 32));
    }
#pragma unroll
    for (int v = 0; v < VV; v++) {
        float val = rr[v] + bias + sx[tid * VP + v];
        rr[v] = val > 0.f ? val : 0.f;
    }

    __syncthreads();   // everyone is done reading sy — safe to reuse as staging
#pragma unroll
    for (int v = 0; v < VV; v++) sy[tid * VP + v] = rr[v];
    __syncthreads();

    for (int i = tid; i < CC * VV; i += 256) {
        int c = i / VV;
        int v = i - c * VV;
        out[base + (long)c * (TT * VV) + v] = sy[c * VP + v];
    }
}

extern "C" void kernel_launch(void* const* d_in, const int* in_sizes, int n_in,
                              void* d_out, int out_size)
{
    // metadata order: t, x, A, w1, b1, w2, b2, w3, b3, w4, b4
    const float* x  = (const float*)d_in[1];
    const float* A  = (const float*)d_in[2];
    const float* w1 = (const float*)d_in[3];
    const float* b1 = (const float*)d_in[4];
    const float* w2 = (const float*)d_in[5];
    const float* b2 = (const float*)d_in[6];
    const float* w3 = (const float*)d_in[7];
    const float* b3 = (const float*)d_in[8];
    const float* w4 = (const float*)d_in[9];
    const float* b4 = (const float*)d_in[10];
    float* out = (float*)d_out;

    float *buf0, *buf1;
    cudaGetSymbolAddress((void**)&buf0, g_buf0);
    cudaGetSymbolAddress((void**)&buf1, g_buf1);

    cudaFuncSetAttribute(ode_block_kernel,
                         cudaFuncAttributeMaxDynamicSharedMemorySize, SMEM_BYTES);

    ode_block_kernel<<<NT, 256, SMEM_BYTES>>>(x,    A, w1, b1, buf0);
    ode_block_kernel<<<NT, 256, SMEM_BYTES>>>(buf0, A, w2, b2, buf1);
    ode_block_kernel<<<NT, 256, SMEM_BYTES>>>(buf1, A, w3, b3, buf0);
    ode_block_kernel<<<NT, 256, SMEM_BYTES>>>(buf0, A, w4, b4, out);
}

// round 3
// speedup vs baseline: 1.1400x; 1.1400x over previous
#include <cuda_runtime.h>

#define NN 64
#define CC 256
#define TT 64
#define VV 25
#define VP 28                  // padded V row (112B, 16B-aligned)
#define NT (NN * TT)
#define ELEMS (NN * CC * TT * VV)

typedef unsigned long long ull;

// Ping-pong scratch for inter-block residual tensors (no cudaMalloc allowed)
__device__ float g_buf0[ELEMS];
__device__ float g_buf1[ELEMS];

// Packed fp32x2 FMA (sm_100+; ptxas never auto-fuses — inline PTX required)
__device__ __forceinline__ ull ffma2(ull a, ull b, ull c) {
    ull d;
    asm("fma.rn.f32x2 %0, %1, %2, %3;" : "=l"(d) : "l"(a), "l"(b), "l"(c));
    return d;
}
__device__ __forceinline__ ull pack2(float x) {
    ull d; unsigned xu = __float_as_uint(x);
    asm("mov.b64 %0, {%1, %2};" : "=l"(d) : "r"(xu), "r"(xu));
    return d;
}
__device__ __forceinline__ ull pack2f(float lo, float hi) {
    ull d;
    asm("mov.b64 %0, {%1, %2};" : "=l"(d) : "r"(__float_as_uint(lo)), "r"(__float_as_uint(hi)));
    return d;
}
__device__ __forceinline__ float lo32(ull a) { return __uint_as_float((unsigned)(a & 0xffffffffULL)); }
__device__ __forceinline__ float hi32(ull a) { return __uint_as_float((unsigned)(a >> 32)); }

// Shared memory layout (floats):
//   sx:  CC*VP = 7168   (x slab / residual)
//   sy:  CC*VP = 7168   (y = x @ A^T, reused as output staging)
//   sAp: 650 (pad 656)  (A packed as v-pair u64: [u][j], row 25 zeroed)
//   wt:  32*258 = 8256  (transposed W tile, even stride => aligned float2 reads)
#define SX_OFF   0
#define SY_OFF   (CC * VP)
#define SAP_OFF  (2 * CC * VP)
#define WT_OFF   (2 * CC * VP + 656)
#define WT_STRIDE 258
#define SMEM_FLOATS (WT_OFF + 32 * WT_STRIDE)
#define SMEM_BYTES  (SMEM_FLOATS * 4)

__global__ void __launch_bounds__(256, 2)
ode_block_kernel(const float* __restrict__ in,   // [N,C,T,V]
                 const float* __restrict__ Amat, // [V,V]
                 const float* __restrict__ w,    // [C,C]
                 const float* __restrict__ b,    // [C]
                 float* __restrict__ out)        // [N,C,T,V]
{
    extern __shared__ float smem[];
    float* sx  = smem + SX_OFF;
    float* sy  = smem + SY_OFF;
    ull*   sAp = (ull*)(smem + SAP_OFF);
    float* wt  = smem + WT_OFF;

    const int tid = threadIdx.x;
    const int n   = blockIdx.x / TT;
    const int t   = blockIdx.x - n * TT;
    const long base = (long)n * (CC * TT * VV) + (long)t * VV;

    // ---- Load A packed (v-pairs along hi/lo, A row 25 = 0) and the x slab ----
    for (int i = tid; i < VV * 13; i += 256) {
        int u = i / 13, j = i - u * 13;
        float lo = Amat[(2 * j) * VV + u];
        float hi = (2 * j + 1 < VV) ? Amat[(2 * j + 1) * VV + u] : 0.f;
        sAp[i] = pack2f(lo, hi);   // layout [u*13 + j]
    }
    for (int i = tid; i < CC * VV; i += 256) {
        int c = i / VV, v = i - c * VV;
        sx[c * VP + v] = in[base + (long)c * (TT * VV) + v];
    }
    __syncthreads();

    // ---- Phase 1: y[c][2j..2j+1] = sum_u {A[2j][u],A[2j+1][u]} * x[c][u], thread c = tid ----
    {
        float4 xr4[7];
        const float4* xp = (const float4*)(sx + tid * VP);
#pragma unroll
        for (int q = 0; q < 7; q++) xr4[q] = xp[q];
        const float* xr = (const float*)xr4;

        ull acc[13];
#pragma unroll
        for (int j = 0; j < 13; j++) acc[j] = 0ULL;
#pragma unroll
        for (int u = 0; u < VV; u++) {
            ull xu2 = pack2(xr[u]);
#pragma unroll
            for (int j = 0; j < 13; j++) acc[j] = ffma2(sAp[u * 13 + j], xu2, acc[j]);
        }
        ull* yo = (ull*)(sy + tid * VP);
#pragma unroll
        for (int j = 0; j < 13; j++) yo[j] = acc[j];  // floats 0..25 (25 is zero via A row 25)
        yo[13] = 0ULL;                                // floats 26,27 = 0
    }
    __syncthreads();

    // ---- Phase 2: v-split + 2 outputs per thread ----
    // p = v-half (floats 16p..16p+11 via float4s, lone u64 at 12+2p)
    // op -> outputs o0=2op, o1=2op+1
    const int p  = tid >> 7;
    const int op = tid & 127;
    const int o0 = 2 * op, o1 = o0 + 1;

    ull a0[7], a1[7];
#pragma unroll
    for (int j = 0; j < 7; j++) { a0[j] = 0ULL; a1[j] = 0ULL; }

    const float* syb = sy + 16 * p;       // base for the 3 x LDS.128
    const float* syu = sy + 12 + 2 * p;   // base for the lone LDS.64

    for (int cc = 0; cc < CC; cc += 32) {
        // stage transposed W tile (gmem read coalesced)
        for (int i = tid; i < 32 * CC; i += 256) {
            int o = i >> 5, cl = i & 31;
            wt[cl * WT_STRIDE + o] = w[o * CC + cc + cl];
        }
        __syncthreads();

#pragma unroll 4
        for (int cl = 0; cl < 32; cl++) {
            const int yb = (cc + cl) * VP;
            const ulonglong2* yq = (const ulonglong2*)(syb + yb);
            ulonglong2 q0 = yq[0];
            ulonglong2 q1 = yq[1];
            ulonglong2 q2 = yq[2];
            ull uY = *(const ull*)(syu + yb);

            float2 wf = *(const float2*)(wt + cl * WT_STRIDE + o0);
            ull w0 = pack2(wf.x), w1 = pack2(wf.y);

            a0[0] = ffma2(q0.x, w0, a0[0]);  a1[0] = ffma2(q0.x, w1, a1[0]);
            a0[1] = ffma2(q0.y, w0, a0[1]);  a1[1] = ffma2(q0.y, w1, a1[1]);
            a0[2] = ffma2(q1.x, w0, a0[2]);  a1[2] = ffma2(q1.x, w1, a1[2]);
            a0[3] = ffma2(q1.y, w0, a0[3]);  a1[3] = ffma2(q1.y, w1, a1[3]);
            a0[4] = ffma2(q2.x, w0, a0[4]);  a1[4] = ffma2(q2.x, w1, a1[4]);
            a0[5] = ffma2(q2.y, w0, a0[5]);  a1[5] = ffma2(q2.y, w1, a1[5]);
            a0[6] = ffma2(uY,   w0, a0[6]);  a1[6] = ffma2(uY,   w1, a1[6]);
        }
        __syncthreads();   // last iteration's sync also protects the staging reuse below
    }

    // ---- Phase 3: epilogue relu(acc + b + residual) -> staging sy ----
    {
        float bias0 = b[o0], bias1 = b[o1];
        float*       s0 = sy + o0 * VP;
        float*       s1 = sy + o1 * VP;
        const float* r0 = sx + o0 * VP;
        const float* r1 = sx + o1 * VP;
        const int fb = 16 * p;
#pragma unroll
        for (int k = 0; k < 6; k++) {
            int f = fb + 2 * k;
            float v00 = lo32(a0[k]) + bias0 + r0[f];
            float v01 = hi32(a0[k]) + bias0 + r0[f + 1];
            s0[f]     = fmaxf(v00, 0.f);
            s0[f + 1] = fmaxf(v01, 0.f);
            float v10 = lo32(a1[k]) + bias1 + r1[f];
            float v11 = hi32(a1[k]) + bias1 + r1[f + 1];
            s1[f]     = fmaxf(v10, 0.f);
            s1[f + 1] = fmaxf(v11, 0.f);
        }
        int f = 12 + 2 * p;
        float v00 = lo32(a0[6]) + bias0 + r0[f];
        float v01 = hi32(a0[6]) + bias0 + r0[f + 1];
        s0[f]     = fmaxf(v00, 0.f);
        s0[f + 1] = fmaxf(v01, 0.f);
        float v10 = lo32(a1[6]) + bias1 + r1[f];
        float v11 = hi32(a1[6]) + bias1 + r1[f + 1];
        s1[f]     = fmaxf(v10, 0.f);
        s1[f + 1] = fmaxf(v11, 0.f);
    }
    __syncthreads();

    // ---- coalesced-ish store ----
    for (int i = tid; i < CC * VV; i += 256) {
        int c = i / VV, v = i - c * VV;
        out[base + (long)c * (TT * VV) + v] = sy[c * VP + v];
    }
}

extern "C" void kernel_launch(void* const* d_in, const int* in_sizes, int n_in,
                              void* d_out, int out_size)
{
    // metadata order: t, x, A, w1, b1, w2, b2, w3, b3, w4, b4
    const float* x  = (const float*)d_in[1];
    const float* A  = (const float*)d_in[2];
    const float* w1 = (const float*)d_in[3];
    const float* b1 = (const float*)d_in[4];
    const float* w2 = (const float*)d_in[5];
    const float* b2 = (const float*)d_in[6];
    const float* w3 = (const float*)d_in[7];
    const float* b3 = (const float*)d_in[8];
    const float* w4 = (const float*)d_in[9];
    const float* b4 = (const float*)d_in[10];
    float* out = (float*)d_out;

    float *buf0, *buf1;
    cudaGetSymbolAddress((void**)&buf0, g_buf0);
    cudaGetSymbolAddress((void**)&buf1, g_buf1);

    cudaFuncSetAttribute(ode_block_kernel,
                         cudaFuncAttributeMaxDynamicSharedMemorySize, SMEM_BYTES);

    ode_block_kernel<<<NT, 256, SMEM_BYTES>>>(x,    A, w1, b1, buf0);
    ode_block_kernel<<<NT, 256, SMEM_BYTES>>>(buf0, A, w2, b2, buf1);
    ode_block_kernel<<<NT, 256, SMEM_BYTES>>>(buf1, A, w3, b3, buf0);
    ode_block_kernel<<<NT, 256, SMEM_BYTES>>>(buf0, A, w4, b4, out);
}

// round 6
// speedup vs baseline: 3.2067x; 2.8129x over previous
#include <cuda_runtime.h>
#include <cuda_bf16.h>
#include <cstdint>

#define NN 64
#define CC 256
#define TT 64
#define VV 25
#define TV 1600
#define ELEMS (NN * CC * TT * VV)

typedef unsigned long long ull;

// Device scratch (no cudaMalloc allowed)
__device__ float g_r0[ELEMS];                    // residual ping
__device__ float g_r1[ELEMS];                    // residual pong
__device__ __nv_bfloat16 g_yhi[ELEMS];           // mixed tensor, bf16 hi
__device__ __nv_bfloat16 g_ylo[ELEMS];           // mixed tensor, bf16 lo
__device__ __nv_bfloat16 g_whi[4 * CC * CC];     // W hi, all 4 layers
__device__ __nv_bfloat16 g_wlo[4 * CC * CC];     // W lo

// ---------------- PTX helpers ----------------
__device__ __forceinline__ uint32_t smem_u32(const void* p) {
    uint32_t a;
    asm("{ .reg .u64 t; cvta.to.shared.u64 t, %1; cvt.u32.u64 %0, t; }" : "=r"(a) : "l"(p));
    return a;
}
__device__ __forceinline__ ull ffma2(ull a, ull b, ull c) {
    ull d; asm("fma.rn.f32x2 %0, %1, %2, %3;" : "=l"(d) : "l"(a), "l"(b), "l"(c)); return d;
}
__device__ __forceinline__ ull pack2(float x) {
    ull d; unsigned xu = __float_as_uint(x);
    asm("mov.b64 %0, {%1, %2};" : "=l"(d) : "r"(xu), "r"(xu)); return d;
}
__device__ __forceinline__ ull pack2f(float lo, float hi) {
    ull d; asm("mov.b64 %0, {%1, %2};" : "=l"(d) : "r"(__float_as_uint(lo)), "r"(__float_as_uint(hi))); return d;
}
__device__ __forceinline__ float lo32(ull a) { return __uint_as_float((unsigned)(a & 0xffffffffULL)); }
__device__ __forceinline__ float hi32(ull a) { return __uint_as_float((unsigned)(a >> 32)); }

__device__ __forceinline__ void ldsm_x4(uint32_t* r, uint32_t addr) {
    asm volatile("ldmatrix.sync.aligned.m8n8.x4.shared.b16 {%0,%1,%2,%3}, [%4];"
                 : "=r"(r[0]), "=r"(r[1]), "=r"(r[2]), "=r"(r[3]) : "r"(addr));
}
__device__ __forceinline__ void ldsm_x4_t(uint32_t* r, uint32_t addr) {
    asm volatile("ldmatrix.sync.aligned.m8n8.x4.trans.shared.b16 {%0,%1,%2,%3}, [%4];"
                 : "=r"(r[0]), "=r"(r[1]), "=r"(r[2]), "=r"(r[3]) : "r"(addr));
}
__device__ __forceinline__ void mma_bf16(float* c, const uint32_t* a, const uint32_t* b) {
    asm volatile("mma.sync.aligned.m16n8k16.row.col.f32.bf16.bf16.f32 "
                 "{%0,%1,%2,%3}, {%4,%5,%6,%7}, {%8,%9}, {%0,%1,%2,%3};"
                 : "+f"(c[0]), "+f"(c[1]), "+f"(c[2]), "+f"(c[3])
                 : "r"(a[0]), "r"(a[1]), "r"(a[2]), "r"(a[3]), "r"(b[0]), "r"(b[1]));
}
__device__ __forceinline__ void cp16(uint32_t dst, const void* src) {
    asm volatile("cp.async.cg.shared.global [%0], [%1], 16;" :: "r"(dst), "l"(src) : "memory");
}
#define CP_COMMIT() asm volatile("cp.async.commit_group;" ::: "memory")

// ---------------- W split kernel (once, all 4 layers) ----------------
__global__ void __launch_bounds__(256)
wsplit_kernel(const float* __restrict__ w0, const float* __restrict__ w1,
              const float* __restrict__ w2, const float* __restrict__ w3,
              __nv_bfloat16* __restrict__ whi, __nv_bfloat16* __restrict__ wlo)
{
    int id = blockIdx.x * 256 + threadIdx.x;      // 0 .. 262143
    const float* ws[4] = { w0, w1, w2, w3 };
    float v = ws[id >> 16][id & 65535];
    __nv_bfloat16 h = __float2bfloat16_rn(v);
    whi[id] = h;
    wlo[id] = __float2bfloat16_rn(v - __bfloat162float(h));
}

// ---------------- Mix kernel: y = A-mix(x), emitted as bf16 hi/lo ----------------
__global__ void __launch_bounds__(256)
mix_kernel(const float* __restrict__ in, const float* __restrict__ Amat,
           __nv_bfloat16* __restrict__ yhi, __nv_bfloat16* __restrict__ ylo)
{
    __shared__ ull sAp[325];          // A packed: [u][j], pair (2j, 2j+1), row 25 = 0
    __shared__ float slab[6400];
    const int tid = threadIdx.x;
    const size_t base = (size_t)blockIdx.x * 6400;

    for (int i = tid; i < 325; i += 256) {
        int u = i / 13, j = i - u * 13;
        float lo = Amat[(2 * j) * VV + u];
        float hi = (2 * j + 1 < VV) ? Amat[(2 * j + 1) * VV + u] : 0.f;
        sAp[i] = pack2f(lo, hi);
    }
    for (int i = tid; i < 6400; i += 256) slab[i] = in[base + i];
    __syncthreads();

    const int rb = tid * 25;
    float xr[VV];
#pragma unroll
    for (int u = 0; u < VV; u++) xr[u] = slab[rb + u];

    ull acc[13];
#pragma unroll
    for (int j = 0; j < 13; j++) acc[j] = 0ULL;
#pragma unroll
    for (int u = 0; u < VV; u++) {
        ull xu2 = pack2(xr[u]);
#pragma unroll
        for (int j = 0; j < 13; j++) acc[j] = ffma2(sAp[u * 13 + j], xu2, acc[j]);
    }
#pragma unroll
    for (int j = 0; j < 12; j++) {
        slab[rb + 2 * j]     = lo32(acc[j]);
        slab[rb + 2 * j + 1] = hi32(acc[j]);
    }
    slab[rb + 24] = lo32(acc[12]);
    __syncthreads();

    uint32_t* yh32 = (uint32_t*)(yhi + base);
    uint32_t* yl32 = (uint32_t*)(ylo + base);
    for (int p = tid; p < 3200; p += 256) {
        float v0 = slab[2 * p], v1 = slab[2 * p + 1];
        __nv_bfloat16 h0 = __float2bfloat16_rn(v0);
        __nv_bfloat16 h1 = __float2bfloat16_rn(v1);
        __nv_bfloat16 l0 = __float2bfloat16_rn(v0 - __bfloat162float(h0));
        __nv_bfloat16 l1 = __float2bfloat16_rn(v1 - __bfloat162float(h1));
        __nv_bfloat162 hh; hh.x = h0; hh.y = h1;
        __nv_bfloat162 ll; ll.x = l0; ll.y = l1;
        yh32[p] = *(uint32_t*)&hh;
        yl32[p] = *(uint32_t*)&ll;
    }
}

// ---------------- GEMM: out = relu(W @ y + b + xres), 3xBF16 mma.sync ----------------
// grid (13, 2, 64): x = col-tile (128 of 1600), y = M-tile (o/128), z = n
// Double-buffered cp.async pipeline. Dynamic smem:
//   per stage: sWh 128x80B, sWl 128x80B, sYh 32x272B, sYl 32x272B
#define WS_STRIDE 80      // 128 rows (o) x 32 c bf16 (64B) + 16B pad
#define YS_STRIDE 272     // 32 rows (c)  x 128 j bf16 (256B) + 16B pad
#define SM_WH 0
#define SM_WL 10240
#define SM_YH 20480
#define SM_YL 29184
#define STAGE_BYTES 37888
#define SM_TOTAL (2 * STAGE_BYTES)   // 75776

__global__ void __launch_bounds__(256, 2)
gemm_kernel(const __nv_bfloat16* __restrict__ yhi, const __nv_bfloat16* __restrict__ ylo,
            const __nv_bfloat16* __restrict__ whi, const __nv_bfloat16* __restrict__ wlo,
            const float* __restrict__ b, const float* __restrict__ xres,
            float* __restrict__ out)
{
    extern __shared__ __align__(16) unsigned char smem[];
    const uint32_t smu = smem_u32(smem);

    const int tid  = threadIdx.x;
    const int lane = tid & 31, wid = tid >> 5;
    const int wm   = wid >> 1, wn = wid & 1;       // warp grid 4 (M) x 2 (N)
    const int ct   = blockIdx.x;
    const int mt   = blockIdx.y;
    const int n    = blockIdx.z;
    const int col0 = ct * 128;

    const __nv_bfloat16* Wh = whi + (size_t)(mt * 128) * CC;
    const __nv_bfloat16* Wl = wlo + (size_t)(mt * 128) * CC;
    const __nv_bfloat16* Yh = yhi + ((size_t)n * CC) * TV + col0;
    const __nv_bfloat16* Yl = ylo + ((size_t)n * CC) * TV + col0;

    // ragged last tile: pre-zero the永-invalid Y region in BOTH stages, skip its cp.asyncs
    if (col0 + 128 > TV) {
        for (int i = tid; i < 1024; i += 256) {
            int stg = i >> 9, hl = (i >> 8) & 1, c = (i >> 3) & 31, jp = 8 + (i & 7);
            uint32_t d = smu + stg * STAGE_BYTES + (hl ? SM_YL : SM_YH)
                       + c * YS_STRIDE + jp * 16;
            asm volatile("st.shared.v4.b32 [%0], {%1,%1,%1,%1};" :: "r"(d), "r"(0) : "memory");
        }
        __syncthreads();
    }

    // issue all cp.asyncs for chunk kc into stage stg (8 x 16B per thread)
    auto issue = [&](int kc, int stg) {
        const int c0 = kc * 32;
        const uint32_t sbase = smu + stg * STAGE_BYTES;
#pragma unroll
        for (int r = 0; r < 2; r++) {
            const int q = tid + r * 256;           // 0..511
            // W tiles: q -> (o, 8-col group)
            const int o = q >> 2, cp4 = q & 3;
            const size_t wsrc = (size_t)o * CC + c0 + cp4 * 8;
            const uint32_t wdst = sbase + o * WS_STRIDE + cp4 * 16;
            cp16(wdst + SM_WH, Wh + wsrc);
            cp16(wdst + SM_WL, Wl + wsrc);
            // Y tiles: q -> (c, 8-col group)
            const int c = q >> 4, jp = q & 15;
            if (col0 + jp * 8 < TV) {
                const size_t ysrc = (size_t)(c0 + c) * TV + jp * 8;
                const uint32_t ydst = sbase + c * YS_STRIDE + jp * 16;
                cp16(ydst + SM_YH, Yh + ysrc);
                cp16(ydst + SM_YL, Yl + ysrc);
            }
        }
    };

    float acc[2][8][4];
#pragma unroll
    for (int fm = 0; fm < 2; fm++)
#pragma unroll
        for (int nb = 0; nb < 8; nb++)
#pragma unroll
            for (int q = 0; q < 4; q++) acc[fm][nb][q] = 0.f;

    issue(0, 0);
    CP_COMMIT();

    for (int kc = 0; kc < 8; kc++) {
        if (kc < 7) {
            issue(kc + 1, (kc + 1) & 1);
            CP_COMMIT();
            asm volatile("cp.async.wait_group 1;" ::: "memory");
        } else {
            asm volatile("cp.async.wait_group 0;" ::: "memory");
        }
        __syncthreads();

        const uint32_t st  = (kc & 1) ? STAGE_BYTES : 0u;
        const uint32_t swh = smu + st + SM_WH;
        const uint32_t swl = smu + st + SM_WL;
        const uint32_t syh = smu + st + SM_YH;
        const uint32_t syl = smu + st + SM_YL;

#pragma unroll
        for (int s = 0; s < 2; s++) {
            uint32_t Ah[2][4], Al[2][4];
            const uint32_t aoff = (uint32_t)(lane & 15) * WS_STRIDE + s * 32 + (lane >> 4) * 16;
            ldsm_x4(Ah[0], swh + (wm * 32 +  0) * WS_STRIDE + aoff);
            ldsm_x4(Ah[1], swh + (wm * 32 + 16) * WS_STRIDE + aoff);
            ldsm_x4(Al[0], swl + (wm * 32 +  0) * WS_STRIDE + aoff);
            ldsm_x4(Al[1], swl + (wm * 32 + 16) * WS_STRIDE + aoff);

            const uint32_t boff = (uint32_t)(s * 16 + (lane & 15)) * YS_STRIDE + (lane >> 4) * 16;
#pragma unroll
            for (int nbp = 0; nbp < 4; nbp++) {
                uint32_t Bh[4], Bl[4];
                const uint32_t bcol = (uint32_t)(wn * 64 + nbp * 16) * 2;
                ldsm_x4_t(Bh, syh + boff + bcol);
                ldsm_x4_t(Bl, syl + boff + bcol);
#pragma unroll
                for (int h = 0; h < 2; h++) {
                    const int nb = nbp * 2 + h;
                    mma_bf16(acc[0][nb], Ah[0], &Bh[2 * h]);
                    mma_bf16(acc[0][nb], Ah[0], &Bl[2 * h]);
                    mma_bf16(acc[0][nb], Al[0], &Bh[2 * h]);
                    mma_bf16(acc[1][nb], Ah[1], &Bh[2 * h]);
                    mma_bf16(acc[1][nb], Ah[1], &Bl[2 * h]);
                    mma_bf16(acc[1][nb], Al[1], &Bh[2 * h]);
                }
            }
        }
        __syncthreads();
    }

    // ---- epilogue: relu(acc + b[o] + xres) straight to gmem ----
    const int g = lane >> 2, tig = lane & 3;
#pragma unroll
    for (int fm = 0; fm < 2; fm++) {
        const int o0 = mt * 128 + wm * 32 + fm * 16 + g;
        const float bias0 = b[o0];
        const float bias1 = b[o0 + 8];
        const float* r0 = xres + ((size_t)n * CC + o0) * TV;
        const float* r1 = r0 + 8 * TV;
        float* p0 = out + ((size_t)n * CC + o0) * TV;
        float* p1 = p0 + 8 * TV;
#pragma unroll
        for (int nb = 0; nb < 8; nb++) {
            const int j = col0 + wn * 64 + nb * 8 + 2 * tig;
            if (j < TV) {
                float2 ra = *(const float2*)(r0 + j);
                float2 rb = *(const float2*)(r1 + j);
                float2 oa, ob;
                oa.x = fmaxf(acc[fm][nb][0] + bias0 + ra.x, 0.f);
                oa.y = fmaxf(acc[fm][nb][1] + bias0 + ra.y, 0.f);
                ob.x = fmaxf(acc[fm][nb][2] + bias1 + rb.x, 0.f);
                ob.y = fmaxf(acc[fm][nb][3] + bias1 + rb.y, 0.f);
                *(float2*)(p0 + j) = oa;
                *(float2*)(p1 + j) = ob;
            }
        }
    }
}

// ---------------- launch ----------------
extern "C" void kernel_launch(void* const* d_in, const int* in_sizes, int n_in,
                              void* d_out, int out_size)
{
    // metadata order: t, x, A, w1, b1, w2, b2, w3, b3, w4, b4
    const float* x  = (const float*)d_in[1];
    const float* A  = (const float*)d_in[2];
    const float* W[4] = { (const float*)d_in[3], (const float*)d_in[5],
                          (const float*)d_in[7], (const float*)d_in[9] };
    const float* B[4] = { (const float*)d_in[4], (const float*)d_in[6],
                          (const float*)d_in[8], (const float*)d_in[10] };
    float* out = (float*)d_out;

    float *r0, *r1;
    __nv_bfloat16 *yhi, *ylo, *whi, *wlo;
    cudaGetSymbolAddress((void**)&r0,  g_r0);
    cudaGetSymbolAddress((void**)&r1,  g_r1);
    cudaGetSymbolAddress((void**)&yhi, g_yhi);
    cudaGetSymbolAddress((void**)&ylo, g_ylo);
    cudaGetSymbolAddress((void**)&whi, g_whi);
    cudaGetSymbolAddress((void**)&wlo, g_wlo);

    cudaFuncSetAttribute(gemm_kernel,
                         cudaFuncAttributeMaxDynamicSharedMemorySize, SM_TOTAL);

    wsplit_kernel<<<1024, 256>>>(W[0], W[1], W[2], W[3], whi, wlo);

    const float* cur = x;
    float* nxt[4] = { r0, r1, r0, out };
    dim3 ggrid(13, 2, NN);

    for (int l = 0; l < 4; l++) {
        mix_kernel<<<4096, 256>>>(cur, A, yhi, ylo);
        gemm_kernel<<<ggrid, 256, SM_TOTAL>>>(yhi, ylo, whi + l * CC * CC, wlo + l * CC * CC,
                                              B[l], cur, nxt[l]);
        cur = nxt[l];
    }
}